// round 1
// baseline (speedup 1.0000x reference)
#include <cuda_runtime.h>
#include <cuda_bf16.h>
#include <cstdint>

// Problem constants
#define N_NODES 50000
#define N_EDGES 800000
#define F0 256
#define F1 256
#define F2 256
#define F3 128

// Scratch (allocation-free rule: __device__ globals)
__device__ float g_tmp[N_NODES * 256];  // gemm output (pre-spmm), max 50000x256
__device__ float g_h[N_NODES * 256];    // spmm output / next layer input

// ---------------------------------------------------------------------------
// Tiled fp32 GEMM:  C[M,N] = op(A)[M,K] @ B[K,N]   (op = optional ReLU on A)
// BM=64, BN=64, BK=16, 256 threads, 4x4 micro-tile per thread.
// ---------------------------------------------------------------------------
template <bool RELU_A>
__global__ __launch_bounds__(256) void gemm_kernel(
    const float* __restrict__ A, const float* __restrict__ B,
    float* __restrict__ C, int M, int N, int K)
{
    constexpr int BM = 64, BN = 64, BK = 16;
    __shared__ float As[BK][BM];   // transposed store: As[k][m]
    __shared__ float Bs[BK][BN];

    const int tid = threadIdx.x;           // 0..255
    const int block_m = blockIdx.y * BM;
    const int block_n = blockIdx.x * BN;

    // thread -> 4x4 micro tile
    const int tm = (tid / 16) * 4;         // 0..60 step 4
    const int tn = (tid % 16) * 4;

    float acc[4][4] = {};

    // load mapping for A tile (BM x BK = 1024 elems, 4 per thread)
    // each thread loads 4 consecutive k's of one row? Better: coalesce on K.
    // A is row-major MxK. Load As[k][m].
    const int a_row = tid / 4;             // 0..63 (m within tile)
    const int a_col = (tid % 4) * 4;       // 0..12 (k within tile, 4 elems)
    // B tile (BK x BN = 1024): coalesce on N
    const int b_row = tid / 16;            // 0..15 (k)
    const int b_col = (tid % 16) * 4;      // n, 4 elems

    for (int k0 = 0; k0 < K; k0 += BK) {
        // load A tile
        {
            int gm = block_m + a_row;
            if (gm < M) {
                const float* ap = A + (size_t)gm * K + k0 + a_col;
                float4 v = *reinterpret_cast<const float4*>(ap);
                if (RELU_A) {
                    v.x = fmaxf(v.x, 0.f); v.y = fmaxf(v.y, 0.f);
                    v.z = fmaxf(v.z, 0.f); v.w = fmaxf(v.w, 0.f);
                }
                As[a_col + 0][a_row] = v.x;
                As[a_col + 1][a_row] = v.y;
                As[a_col + 2][a_row] = v.z;
                As[a_col + 3][a_row] = v.w;
            } else {
                As[a_col + 0][a_row] = 0.f;
                As[a_col + 1][a_row] = 0.f;
                As[a_col + 2][a_row] = 0.f;
                As[a_col + 3][a_row] = 0.f;
            }
        }
        // load B tile (K and N are multiples of 16/64 here; no guard needed)
        {
            const float* bp = B + (size_t)(k0 + b_row) * N + block_n + b_col;
            float4 v = *reinterpret_cast<const float4*>(bp);
            Bs[b_row][b_col + 0] = v.x;
            Bs[b_row][b_col + 1] = v.y;
            Bs[b_row][b_col + 2] = v.z;
            Bs[b_row][b_col + 3] = v.w;
        }
        __syncthreads();

        #pragma unroll
        for (int kk = 0; kk < BK; kk++) {
            float ra[4], rb[4];
            #pragma unroll
            for (int i = 0; i < 4; i++) ra[i] = As[kk][tm + i];
            #pragma unroll
            for (int j = 0; j < 4; j++) rb[j] = Bs[kk][tn + j];
            #pragma unroll
            for (int i = 0; i < 4; i++)
                #pragma unroll
                for (int j = 0; j < 4; j++)
                    acc[i][j] = fmaf(ra[i], rb[j], acc[i][j]);
        }
        __syncthreads();
    }

    // store
    #pragma unroll
    for (int i = 0; i < 4; i++) {
        int gm = block_m + tm + i;
        if (gm < M) {
            float4 v = make_float4(acc[i][0], acc[i][1], acc[i][2], acc[i][3]);
            *reinterpret_cast<float4*>(C + (size_t)gm * N + block_n + tn) = v;
        }
    }
}

// ---------------------------------------------------------------------------
// Init destination rows to bias (broadcast per column)
// ---------------------------------------------------------------------------
__global__ void init_bias_kernel(float* __restrict__ out,
                                 const float* __restrict__ b, int M, int N)
{
    int idx = blockIdx.x * blockDim.x + threadIdx.x;
    int total = M * N / 4;
    if (idx >= total) return;
    int j4 = idx % (N / 4);
    float4 bv = reinterpret_cast<const float4*>(b)[j4];
    reinterpret_cast<float4*>(out)[idx] = bv;
}

// ---------------------------------------------------------------------------
// Edge-parallel SpMM scatter: out[rows[e]] += vals[e] * h[cols[e]]
// One thread per (edge, float4 chunk). red.global.add.v4.f32 (no return).
// K4_SHIFT = log2(K/4): 6 for K=256, 5 for K=128.
// ---------------------------------------------------------------------------
template <int K4_SHIFT>
__global__ __launch_bounds__(256) void spmm_kernel(
    const float* __restrict__ h, const float* __restrict__ vals,
    const int* __restrict__ rows, const int* __restrict__ cols,
    float* __restrict__ out)
{
    constexpr int K4 = 1 << K4_SHIFT;
    int idx = blockIdx.x * blockDim.x + threadIdx.x;
    if (idx >= N_EDGES * K4) return;
    int e = idx >> K4_SHIFT;
    int c = idx & (K4 - 1);

    float v = __ldg(&vals[e]);
    int col = __ldg(&cols[e]);
    int row = __ldg(&rows[e]);

    float4 hv = __ldg(reinterpret_cast<const float4*>(h) + ((size_t)col << K4_SHIFT) + c);
    float4 r = make_float4(v * hv.x, v * hv.y, v * hv.z, v * hv.w);

    float* p = out + (((size_t)row << K4_SHIFT) + c) * 4;
    asm volatile("red.global.add.v4.f32 [%0], {%1, %2, %3, %4};"
                 :: "l"(p), "f"(r.x), "f"(r.y), "f"(r.z), "f"(r.w)
                 : "memory");
}

// ---------------------------------------------------------------------------
// Launch
// ---------------------------------------------------------------------------
extern "C" void kernel_launch(void* const* d_in, const int* in_sizes, int n_in,
                              void* d_out, int out_size)
{
    const float* x        = (const float*)d_in[0];
    const float* adj_vals = (const float*)d_in[1];
    const int*   rows     = (const int*)  d_in[2];
    const int*   cols     = (const int*)  d_in[3];
    const float* W1       = (const float*)d_in[4];
    const float* b1       = (const float*)d_in[5];
    const float* W2       = (const float*)d_in[6];
    const float* b2       = (const float*)d_in[7];
    const float* W3       = (const float*)d_in[8];
    const float* b3       = (const float*)d_in[9];
    float* out = (float*)d_out;

    float* tmp; cudaGetSymbolAddress((void**)&tmp, g_tmp);
    float* h;   cudaGetSymbolAddress((void**)&h,   g_h);

    const int M = N_NODES;

    dim3 gemm_block(256);
    dim3 gemm_grid_256((256 + 63) / 64, (M + 63) / 64);   // N=256 tiles
    dim3 gemm_grid_128((128 + 63) / 64, (M + 63) / 64);   // N=128 tiles

    int spmm_threads_256 = N_EDGES * (256 / 4);
    int spmm_threads_128 = N_EDGES * (128 / 4);
    int spmm_blocks_256 = (spmm_threads_256 + 255) / 256;
    int spmm_blocks_128 = (spmm_threads_128 + 255) / 256;

    int init_blocks_256 = (M * 256 / 4 + 255) / 256;
    int init_blocks_128 = (M * 128 / 4 + 255) / 256;

    // Layer 1: tmp = x @ W1 ; h = b1 ; h += spmm(tmp)   (relu deferred to next A-load)
    gemm_kernel<false><<<gemm_grid_256, gemm_block>>>(x, W1, tmp, M, 256, 256);
    init_bias_kernel<<<init_blocks_256, 256>>>(h, b1, M, 256);
    spmm_kernel<6><<<spmm_blocks_256, 256>>>(tmp, adj_vals, rows, cols, h);

    // Layer 2: tmp = relu(h) @ W2 ; h = b2 ; h += spmm(tmp)
    gemm_kernel<true><<<gemm_grid_256, gemm_block>>>(h, W2, tmp, M, 256, 256);
    init_bias_kernel<<<init_blocks_256, 256>>>(h, b2, M, 256);
    spmm_kernel<6><<<spmm_blocks_256, 256>>>(tmp, adj_vals, rows, cols, h);

    // Layer 3: tmp = relu(h) @ W3 ; out = b3 ; out += spmm(tmp)
    gemm_kernel<true><<<gemm_grid_128, gemm_block>>>(h, W3, tmp, M, 128, 256);
    init_bias_kernel<<<init_blocks_128, 256>>>(out, b3, M, 128);
    spmm_kernel<5><<<spmm_blocks_128, 256>>>(tmp, adj_vals, rows, cols, out);
}